// round 15
// baseline (speedup 1.0000x reference)
#include <cuda_runtime.h>
#include <cuda_fp16.h>

// ---------------------------------------------------------------- constants
#define NB_   512      // B*C batch slices
#define HW_   2304     // H*W
#define JJ_   110592   // D*H*W
#define RS_   32
#define RSQ_  1024
#define OUT_  1024
#define BB_   16
#define KK_   32768    // C*R*R

#define KS_   16               // K splits
#define KPC_  (JJ_ / KS_)      // 6912 per CTA
#define KTL_  128              // k per tile
#define TILES_ (KPC_ / KTL_)   // 54 tiles of 128

#define KCP_  128              // proj k-chunks (2048 CTAs)
#define KCLP_ (KK_ / KCP_)     // 256

// ---------------------------------------------------------------- scratch
__device__ float  g_T  [HW_ * RS_];               // t[p][r]
__device__ __half g_Ttrh[RS_ * (size_t)JJ_];      // fp16 Tt transposed: [r][j]
__device__ float  g_Gp [KS_ * (size_t)NB_ * RSQ_];// Gram partials
__device__ float  g_G  [NB_ * RSQ_];              // Gram results
__device__ float  g_part[KCP_ * BB_ * OUT_];      // projection partials

// ---------------------------------------------------------------- helpers
__device__ __forceinline__ void cp16(void* sdst, const void* gsrc) {
    unsigned s = (unsigned)__cvta_generic_to_shared(sdst);
    asm volatile("cp.async.cg.shared.global [%0], [%1], 16;" :: "r"(s), "l"(gsrc));
}

// fp16 inputs, fp32 accumulate
#define MMAF(D, A, B) \
    asm volatile("mma.sync.aligned.m16n8k16.row.col.f32.f16.f16.f32 " \
                 "{%0,%1,%2,%3}, {%4,%5,%6,%7}, {%8,%9}, {%0,%1,%2,%3};" \
                 : "+f"((D)[0]), "+f"((D)[1]), "+f"((D)[2]), "+f"((D)[3]) \
                 : "r"((A)[0]), "r"((A)[1]), "r"((A)[2]), "r"((A)[3]), \
                   "r"((B)[0]), "r"((B)[1]))

// ---------------------------------------------------------------- prep
// t[p,r] = sum_s core2[r,h,s] * core3[s,w,0]
__global__ void k_t(const float* __restrict__ core2, const float* __restrict__ core3) {
    int idx = blockIdx.x * blockDim.x + threadIdx.x;
    if (idx >= HW_ * RS_) return;
    int r = idx & 31;
    int p = idx >> 5;
    int h = p / 48, w = p % 48;
    const float* c2 = core2 + (r * 48 + h) * 32;
    float s = 0.f;
#pragma unroll
    for (int si = 0; si < 32; si++) s += c2[si] * core3[si * 48 + w];
    g_T[p * 32 + r] = s;
}

// Ttrh[r][j] = fp16( core1[d,r] * t[p,r] ),  j = d*HW + p
__global__ void k_ttr(const float* __restrict__ core1) {
    int j = blockIdx.x * 256 + threadIdx.x;
    int r = blockIdx.y;
    int d = j / HW_;
    int p = j - d * HW_;
    g_Ttrh[(size_t)r * JJ_ + j] = __float2half_rn(core1[d * 32 + r] * g_T[p * 32 + r]);
}

// ---------------------------------------------------------------- gram (mma.sync)
// V[k,r] = fp16(x[k]) * fp16(Tt[k,r]) (HMUL2); G = V^T V.
// 6 upper m16n8 tiles, fp32 accumulate; lower triangle mirrored at writeout.
// 128-k tiles, 3-stage cp.async ring, prefetch distance 2, ONE barrier/tile.
__global__ void __launch_bounds__(256, 4) k_gram(const float* __restrict__ x) {
    __shared__ __half sTt[3][32][136];  // stride 136 halves (272B): conflict-free LDS.32
    __shared__ float  sX [3][8][128];

    int tid = threadIdx.x;
    int w   = tid >> 5;
    int l   = tid & 31;
    int n0  = blockIdx.x * 8;
    int ks  = blockIdx.y;
    size_t j0 = (size_t)ks * KPC_;

    int g   = l >> 2;          // row group 0..7
    int tg2 = (l & 3) * 2;     // col pair base

    float acc[6][4];
#pragma unroll
    for (int i = 0; i < 6; i++)
#pragma unroll
        for (int j = 0; j < 4; j++) acc[i][j] = 0.f;

    auto issue = [&](int t, int b) {
        size_t jt = j0 + (size_t)t * KTL_;
        // sTt: 32 rows x 16 chunks of 16B (fp16 row = 256B) = 512 chunks
        {
            int row = tid >> 3, ch = tid & 7;
            cp16(&sTt[b][row][ch * 8], g_Ttrh + (size_t)row * JJ_ + jt + ch * 8);
            cp16(&sTt[b][row][(ch + 8) * 8], g_Ttrh + (size_t)row * JJ_ + jt + (ch + 8) * 8);
        }
        // sX: 8 rows x 32 chunks of 16B = 256 chunks
        {
            int row = tid >> 5, ch = tid & 31;
            cp16(&sX[b][row][ch * 4], x + (size_t)(n0 + row) * JJ_ + jt + ch * 4);
        }
        asm volatile("cp.async.commit_group;" ::: "memory");
    };

    issue(0, 0);
    issue(1, 1);

    for (int t = 0; t < TILES_; t++) {
        int b = t % 3;
        asm volatile("cp.async.wait_group 1;" ::: "memory");
        __syncthreads();
        if (t + 2 < TILES_) issue(t + 2, (t + 2) % 3);
        else asm volatile("cp.async.commit_group;" ::: "memory");  // uniform group count

#pragma unroll
        for (int kk = 0; kk < 8; kk++) {
            int kb = kk * 16;
            float2 xA = *(const float2*)&sX[b][w][kb + tg2];
            float2 xB = *(const float2*)&sX[b][w][kb + tg2 + 8];
            __half2 xhA = __floats2half2_rn(xA.x, xA.y);   // low = even k
            __half2 xhB = __floats2half2_rn(xB.x, xB.y);

            unsigned ah[2][4];
#pragma unroll
            for (int rr = 0; rr < 4; rr++) {       // rows g, g+8, g+16, g+24
                int row = g + 8 * rr;
                __half2 tA = *(const __half2*)&sTt[b][row][kb + tg2];
                __half2 tB = *(const __half2*)&sTt[b][row][kb + tg2 + 8];
                __half2 hA = __hmul2(xhA, tA);
                __half2 hB = __hmul2(xhB, tB);
                int mt = rr >> 1, rg = rr & 1;
                ah[mt][rg]     = *reinterpret_cast<unsigned*>(&hA);
                ah[mt][rg + 2] = *reinterpret_cast<unsigned*>(&hB);
            }
            // B fragments are register subsets of A fragments (Gram property)
            unsigned bh[4][2] = {{ah[0][0], ah[0][2]}, {ah[0][1], ah[0][3]},
                                 {ah[1][0], ah[1][2]}, {ah[1][1], ah[1][3]}};

            // upper tiles: (0,0)(0,1)(0,2)(0,3)(1,2)(1,3); (1,0)(1,1) mirror of (0,2)(0,3)
            MMAF(acc[0], ah[0], bh[0]);
            MMAF(acc[1], ah[0], bh[1]);
            MMAF(acc[2], ah[0], bh[2]);
            MMAF(acc[3], ah[0], bh[3]);
            MMAF(acc[4], ah[1], bh[2]);
            MMAF(acc[5], ah[1], bh[3]);
        }
    }

    // --- writeout partial Gram (mirror upper-right tiles to lower-left)
    float* P = g_Gp + ((size_t)ks * NB_ + n0 + w) * RSQ_;
    const int mt_of[6] = {0, 0, 0, 0, 1, 1};
    const int nt_of[6] = {0, 1, 2, 3, 2, 3};
#pragma unroll
    for (int ti = 0; ti < 6; ti++) {
        int r0 = mt_of[ti] * 16 + g;
        int r1 = r0 + 8;
        int q  = nt_of[ti] * 8 + tg2;
        P[r0 * 32 + q]     = acc[ti][0];
        P[r0 * 32 + q + 1] = acc[ti][1];
        P[r1 * 32 + q]     = acc[ti][2];
        P[r1 * 32 + q + 1] = acc[ti][3];
        if (ti == 2 || ti == 3) {
            P[q * 32 + r0]       = acc[ti][0];
            P[(q + 1) * 32 + r0] = acc[ti][1];
            P[q * 32 + r1]       = acc[ti][2];
            P[(q + 1) * 32 + r1] = acc[ti][3];
        }
    }
}

// sum K-split partials (float2 per thread -> 1024 blocks for occupancy/BW)
__global__ void k_gsum() {
    int i2 = blockIdx.x * 256 + threadIdx.x;   // over 512*1024/2 float2s
    float2 s = {0.f, 0.f};
#pragma unroll
    for (int p = 0; p < KS_; p++) {
        float2 v = *((const float2*)(g_Gp + (size_t)p * NB_ * RSQ_) + i2);
        s.x += v.x; s.y += v.y;
    }
    *((float2*)g_G + i2) = s;
}

// ---------------------------------------------------------------- projection
// grid (16 ot, 128 kc) = 2048 blocks; 64-wide k step for deep DRAM MLP
__global__ void __launch_bounds__(256) k_proj(const float* __restrict__ projw) {
    __shared__ float sw[64][65];
    __shared__ float sf[16][65];
    int ot  = blockIdx.x;
    int kc  = blockIdx.y;
    int tid = threadIdx.x;
    int o0  = ot * 64;
    int b   = tid >> 4;
    int oo  = tid & 15;

    float acc[4] = {0.f, 0.f, 0.f, 0.f};

    for (int kt = 0; kt < KCLP_; kt += 64) {
        int kbase = kc * KCLP_ + kt;
        {
            // W tile: 64 rows x 64 cols; thread -> row tid>>2, 16 cols at (tid&3)*16
            int orow = tid >> 2;
            int part = tid & 3;
            const float4* src = (const float4*)(projw + (size_t)(o0 + orow) * KK_ + kbase + part * 16);
            float4 v0 = src[0], v1 = src[1], v2 = src[2], v3 = src[3];
            float* drow = &sw[orow][part * 16];
            drow[0]  = v0.x; drow[1]  = v0.y; drow[2]  = v0.z; drow[3]  = v0.w;
            drow[4]  = v1.x; drow[5]  = v1.y; drow[6]  = v1.z; drow[7]  = v1.w;
            drow[8]  = v2.x; drow[9]  = v2.y; drow[10] = v2.z; drow[11] = v2.w;
            drow[12] = v3.x; drow[13] = v3.y; drow[14] = v3.z; drow[15] = v3.w;
        }
        {
            // G tile: 16 rows x 64 cols; thread -> row tid>>4, 4 cols at (tid&15)*4
            int frow = tid >> 4;
            int fcol = (tid & 15) * 4;
            float4 v = *(const float4*)(g_G + (size_t)frow * KK_ + kbase + fcol);
            sf[frow][fcol]     = v.x;
            sf[frow][fcol + 1] = v.y;
            sf[frow][fcol + 2] = v.z;
            sf[frow][fcol + 3] = v.w;
        }
        __syncthreads();
#pragma unroll
        for (int k = 0; k < 64; k++) {
            float fv = sf[b][k];
            acc[0] += fv * sw[oo * 4 + 0][k];
            acc[1] += fv * sw[oo * 4 + 1][k];
            acc[2] += fv * sw[oo * 4 + 2][k];
            acc[3] += fv * sw[oo * 4 + 3][k];
        }
        __syncthreads();
    }
#pragma unroll
    for (int j = 0; j < 4; j++)
        g_part[(size_t)kc * (BB_ * OUT_) + b * OUT_ + o0 + oo * 4 + j] = acc[j];
}

__global__ void k_final(const float* __restrict__ projb, float* __restrict__ out) {
    int idx = blockIdx.x * blockDim.x + threadIdx.x;
    if (idx >= BB_ * OUT_) return;
    float s = projb[idx & (OUT_ - 1)];
#pragma unroll
    for (int kc = 0; kc < KCP_; kc++) s += g_part[kc * (BB_ * OUT_) + idx];
    out[idx] = s;
}

// ---------------------------------------------------------------- launch
extern "C" void kernel_launch(void* const* d_in, const int* in_sizes, int n_in,
                              void* d_out, int out_size) {
    const float* x     = (const float*)d_in[0];
    const float* core1 = (const float*)d_in[1];
    const float* core2 = (const float*)d_in[2];
    const float* core3 = (const float*)d_in[3];
    const float* projw = (const float*)d_in[4];
    const float* projb = (const float*)d_in[5];
    float* out = (float*)d_out;

    k_t<<<(HW_ * RS_ + 255) / 256, 256>>>(core2, core3);
    dim3 tg(JJ_ / 256, RS_);
    k_ttr<<<tg, 256>>>(core1);
    dim3 gg(NB_ / 8, KS_);
    k_gram<<<gg, 256>>>(x);
    k_gsum<<<(NB_ * RSQ_) / 512, 256>>>();
    dim3 pg(16, KCP_);
    k_proj<<<pg, 256>>>(projw);
    k_final<<<(BB_ * OUT_ + 255) / 256, 256>>>(projb, out);
}

// round 16
// speedup vs baseline: 1.0243x; 1.0243x over previous
#include <cuda_runtime.h>
#include <cuda_fp16.h>

// ---------------------------------------------------------------- constants
#define NB_   512      // B*C batch slices
#define HW_   2304     // H*W
#define JJ_   110592   // D*H*W
#define RS_   32
#define RSQ_  1024
#define OUT_  1024
#define BB_   16
#define KK_   32768    // C*R*R

#define KS_   16               // K splits
#define KPC_  (JJ_ / KS_)      // 6912 per CTA
#define KTL_  128              // k per tile
#define TILES_ (KPC_ / KTL_)   // 54 tiles of 128

#define KCP_  128              // proj k-chunks (2048 CTAs)
#define KCLP_ (KK_ / KCP_)     // 256

// ---------------------------------------------------------------- scratch
__device__ float  g_T  [HW_ * RS_];               // t[p][r]
__device__ __half g_Ttrh[RS_ * (size_t)JJ_];      // fp16 Tt transposed: [r][j]
__device__ float  g_Gp [KS_ * (size_t)NB_ * RSQ_];// Gram partials
__device__ float  g_G  [NB_ * RSQ_];              // Gram results
__device__ float  g_part[KCP_ * BB_ * OUT_];      // projection partials

// ---------------------------------------------------------------- helpers
__device__ __forceinline__ void cp16(void* sdst, const void* gsrc) {
    unsigned s = (unsigned)__cvta_generic_to_shared(sdst);
    asm volatile("cp.async.cg.shared.global [%0], [%1], 16;" :: "r"(s), "l"(gsrc));
}

// fp16 inputs, fp32 accumulate
#define MMAF(D, A, B) \
    asm volatile("mma.sync.aligned.m16n8k16.row.col.f32.f16.f16.f32 " \
                 "{%0,%1,%2,%3}, {%4,%5,%6,%7}, {%8,%9}, {%0,%1,%2,%3};" \
                 : "+f"((D)[0]), "+f"((D)[1]), "+f"((D)[2]), "+f"((D)[3]) \
                 : "r"((A)[0]), "r"((A)[1]), "r"((A)[2]), "r"((A)[3]), \
                   "r"((B)[0]), "r"((B)[1]))

// ---------------------------------------------------------------- prep
// t[p,r] = sum_s core2[r,h,s] * core3[s,w,0]
__global__ void k_t(const float* __restrict__ core2, const float* __restrict__ core3) {
    int idx = blockIdx.x * blockDim.x + threadIdx.x;
    if (idx >= HW_ * RS_) return;
    int r = idx & 31;
    int p = idx >> 5;
    int h = p / 48, w = p % 48;
    const float* c2 = core2 + (r * 48 + h) * 32;
    float s = 0.f;
#pragma unroll
    for (int si = 0; si < 32; si++) s += c2[si] * core3[si * 48 + w];
    g_T[p * 32 + r] = s;
}

// Ttrh[r][j] = fp16( core1[d,r] * t[p,r] ),  j = d*HW + p
__global__ void k_ttr(const float* __restrict__ core1) {
    int j = blockIdx.x * 256 + threadIdx.x;
    int r = blockIdx.y;
    int d = j / HW_;
    int p = j - d * HW_;
    g_Ttrh[(size_t)r * JJ_ + j] = __float2half_rn(core1[d * 32 + r] * g_T[p * 32 + r]);
}

// ---------------------------------------------------------------- gram (mma.sync)
// V[k,r] = fp16(x[k]) * fp16(Tt[k,r]) (HMUL2); G = V^T V.
// 6 upper m16n8 tiles, fp32 accumulate; lower triangle mirrored at writeout.
// 128-k tiles, 3-stage cp.async ring, prefetch distance 2, ONE barrier/tile.
__global__ void __launch_bounds__(256, 4) k_gram(const float* __restrict__ x) {
    __shared__ __half sTt[3][32][136];  // stride 136 halves (272B): conflict-free LDS.32
    __shared__ float  sX [3][8][128];

    int tid = threadIdx.x;
    int w   = tid >> 5;
    int l   = tid & 31;
    int n0  = blockIdx.x * 8;
    int ks  = blockIdx.y;
    size_t j0 = (size_t)ks * KPC_;

    int g   = l >> 2;          // row group 0..7
    int tg2 = (l & 3) * 2;     // col pair base

    float acc[6][4];
#pragma unroll
    for (int i = 0; i < 6; i++)
#pragma unroll
        for (int j = 0; j < 4; j++) acc[i][j] = 0.f;

    auto issue = [&](int t, int b) {
        size_t jt = j0 + (size_t)t * KTL_;
        // sTt: 32 rows x 16 chunks of 16B (fp16 row = 256B) = 512 chunks
        {
            int row = tid >> 3, ch = tid & 7;
            cp16(&sTt[b][row][ch * 8], g_Ttrh + (size_t)row * JJ_ + jt + ch * 8);
            cp16(&sTt[b][row][(ch + 8) * 8], g_Ttrh + (size_t)row * JJ_ + jt + (ch + 8) * 8);
        }
        // sX: 8 rows x 32 chunks of 16B = 256 chunks
        {
            int row = tid >> 5, ch = tid & 31;
            cp16(&sX[b][row][ch * 4], x + (size_t)(n0 + row) * JJ_ + jt + ch * 4);
        }
        asm volatile("cp.async.commit_group;" ::: "memory");
    };

    issue(0, 0);
    issue(1, 1);

    for (int t = 0; t < TILES_; t++) {
        int b = t % 3;
        asm volatile("cp.async.wait_group 1;" ::: "memory");
        __syncthreads();
        if (t + 2 < TILES_) issue(t + 2, (t + 2) % 3);
        else asm volatile("cp.async.commit_group;" ::: "memory");  // uniform group count

#pragma unroll
        for (int kk = 0; kk < 8; kk++) {
            int kb = kk * 16;
            float2 xA = *(const float2*)&sX[b][w][kb + tg2];
            float2 xB = *(const float2*)&sX[b][w][kb + tg2 + 8];
            __half2 xhA = __floats2half2_rn(xA.x, xA.y);   // low = even k
            __half2 xhB = __floats2half2_rn(xB.x, xB.y);

            unsigned ah[2][4];
#pragma unroll
            for (int rr = 0; rr < 4; rr++) {       // rows g, g+8, g+16, g+24
                int row = g + 8 * rr;
                __half2 tA = *(const __half2*)&sTt[b][row][kb + tg2];
                __half2 tB = *(const __half2*)&sTt[b][row][kb + tg2 + 8];
                __half2 hA = __hmul2(xhA, tA);
                __half2 hB = __hmul2(xhB, tB);
                int mt = rr >> 1, rg = rr & 1;
                ah[mt][rg]     = *reinterpret_cast<unsigned*>(&hA);
                ah[mt][rg + 2] = *reinterpret_cast<unsigned*>(&hB);
            }
            // B fragments are register subsets of A fragments (Gram property)
            unsigned bh[4][2] = {{ah[0][0], ah[0][2]}, {ah[0][1], ah[0][3]},
                                 {ah[1][0], ah[1][2]}, {ah[1][1], ah[1][3]}};

            // upper tiles: (0,0)(0,1)(0,2)(0,3)(1,2)(1,3); (1,0)(1,1) mirror of (0,2)(0,3)
            MMAF(acc[0], ah[0], bh[0]);
            MMAF(acc[1], ah[0], bh[1]);
            MMAF(acc[2], ah[0], bh[2]);
            MMAF(acc[3], ah[0], bh[3]);
            MMAF(acc[4], ah[1], bh[2]);
            MMAF(acc[5], ah[1], bh[3]);
        }
    }

    // --- writeout partial Gram (mirror upper-right tiles to lower-left)
    float* P = g_Gp + ((size_t)ks * NB_ + n0 + w) * RSQ_;
    const int mt_of[6] = {0, 0, 0, 0, 1, 1};
    const int nt_of[6] = {0, 1, 2, 3, 2, 3};
#pragma unroll
    for (int ti = 0; ti < 6; ti++) {
        int r0 = mt_of[ti] * 16 + g;
        int r1 = r0 + 8;
        int q  = nt_of[ti] * 8 + tg2;
        P[r0 * 32 + q]     = acc[ti][0];
        P[r0 * 32 + q + 1] = acc[ti][1];
        P[r1 * 32 + q]     = acc[ti][2];
        P[r1 * 32 + q + 1] = acc[ti][3];
        if (ti == 2 || ti == 3) {
            P[q * 32 + r0]       = acc[ti][0];
            P[(q + 1) * 32 + r0] = acc[ti][1];
            P[q * 32 + r1]       = acc[ti][2];
            P[(q + 1) * 32 + r1] = acc[ti][3];
        }
    }
}

// sum K-split partials (float2 per thread -> 1024 blocks for occupancy/BW)
__global__ void k_gsum() {
    int i2 = blockIdx.x * 256 + threadIdx.x;   // over 512*1024/2 float2s
    float2 s = {0.f, 0.f};
#pragma unroll
    for (int p = 0; p < KS_; p++) {
        float2 v = *((const float2*)(g_Gp + (size_t)p * NB_ * RSQ_) + i2);
        s.x += v.x; s.y += v.y;
    }
    *((float2*)g_G + i2) = s;
}

// ---------------------------------------------------------------- projection
// grid (16 ot, 128 kc) = 2048 blocks; 32-k steps, register-prefetch pipeline:
// regs(t)->smem -> sync -> issue LDG(t+1) -> compute(t) -> sync.
__global__ void __launch_bounds__(256) k_proj(const float* __restrict__ projw) {
    __shared__ float sw[64][33];
    __shared__ float sf[16][33];
    int ot  = blockIdx.x;
    int kc  = blockIdx.y;
    int tid = threadIdx.x;
    int o0  = ot * 64;
    int b   = tid >> 4;
    int oo  = tid & 15;

    int orow = tid >> 2;
    int part = tid & 3;
    int frow = tid >> 4;
    int fcol = (tid & 15) * 2;

    float acc[4] = {0.f, 0.f, 0.f, 0.f};

    float4 w0, w1;
    float2 gv;
    auto ldg = [&](int kbase) {
        const float4* src = (const float4*)(projw + (size_t)(o0 + orow) * KK_ + kbase + part * 8);
        w0 = src[0];
        w1 = src[1];
        gv = *(const float2*)(g_G + (size_t)frow * KK_ + kbase + fcol);
    };

    ldg(kc * KCLP_);

    for (int kt = 0; kt < KCLP_; kt += 32) {
        // store prefetched regs into smem
        {
            float* drow = &sw[orow][part * 8];
            drow[0] = w0.x; drow[1] = w0.y; drow[2] = w0.z; drow[3] = w0.w;
            drow[4] = w1.x; drow[5] = w1.y; drow[6] = w1.z; drow[7] = w1.w;
            sf[frow][fcol]     = gv.x;
            sf[frow][fcol + 1] = gv.y;
        }
        __syncthreads();
        if (kt + 32 < KCLP_) ldg(kc * KCLP_ + kt + 32);  // lands under compute
#pragma unroll
        for (int k = 0; k < 32; k++) {
            float fv = sf[b][k];
            acc[0] += fv * sw[oo * 4 + 0][k];
            acc[1] += fv * sw[oo * 4 + 1][k];
            acc[2] += fv * sw[oo * 4 + 2][k];
            acc[3] += fv * sw[oo * 4 + 3][k];
        }
        __syncthreads();
    }
#pragma unroll
    for (int j = 0; j < 4; j++)
        g_part[(size_t)kc * (BB_ * OUT_) + b * OUT_ + o0 + oo * 4 + j] = acc[j];
}

__global__ void k_final(const float* __restrict__ projb, float* __restrict__ out) {
    int idx = blockIdx.x * blockDim.x + threadIdx.x;
    if (idx >= BB_ * OUT_) return;
    float s = projb[idx & (OUT_ - 1)];
#pragma unroll
    for (int kc = 0; kc < KCP_; kc++) s += g_part[kc * (BB_ * OUT_) + idx];
    out[idx] = s;
}

// ---------------------------------------------------------------- launch
extern "C" void kernel_launch(void* const* d_in, const int* in_sizes, int n_in,
                              void* d_out, int out_size) {
    const float* x     = (const float*)d_in[0];
    const float* core1 = (const float*)d_in[1];
    const float* core2 = (const float*)d_in[2];
    const float* core3 = (const float*)d_in[3];
    const float* projw = (const float*)d_in[4];
    const float* projb = (const float*)d_in[5];
    float* out = (float*)d_out;

    k_t<<<(HW_ * RS_ + 255) / 256, 256>>>(core2, core3);
    dim3 tg(JJ_ / 256, RS_);
    k_ttr<<<tg, 256>>>(core1);
    dim3 gg(NB_ / 8, KS_);
    k_gram<<<gg, 256>>>(x);
    k_gsum<<<(NB_ * RSQ_) / 512, 256>>>();
    dim3 pg(16, KCP_);
    k_proj<<<pg, 256>>>(projw);
    k_final<<<(BB_ * OUT_ + 255) / 256, 256>>>(projb, out);
}

// round 17
// speedup vs baseline: 1.0282x; 1.0038x over previous
#include <cuda_runtime.h>
#include <cuda_fp16.h>

// ---------------------------------------------------------------- constants
#define NB_   512      // B*C batch slices
#define HW_   2304     // H*W
#define JJ_   110592   // D*H*W
#define RS_   32
#define RSQ_  1024
#define OUT_  1024
#define BB_   16
#define KK_   32768    // C*R*R

#define KS_   16               // K splits
#define KPC_  (JJ_ / KS_)      // 6912 per CTA
#define KTL_  128              // k per tile
#define TILES_ (KPC_ / KTL_)   // 54 tiles of 128

#define KCP_  256              // proj k-chunks (4096 CTAs)
#define KCLP_ (KK_ / KCP_)     // 128

// ---------------------------------------------------------------- scratch
__device__ float  g_T  [HW_ * RS_];               // t[p][r]
__device__ __half g_Ttrh[RS_ * (size_t)JJ_];      // fp16 Tt transposed: [r][j]
__device__ float  g_Gp [KS_ * (size_t)NB_ * RSQ_];// Gram partials
__device__ float  g_G  [NB_ * RSQ_];              // Gram results
__device__ float  g_part[KCP_ * BB_ * OUT_];      // projection partials

// ---------------------------------------------------------------- helpers
__device__ __forceinline__ void cp16(void* sdst, const void* gsrc) {
    unsigned s = (unsigned)__cvta_generic_to_shared(sdst);
    asm volatile("cp.async.cg.shared.global [%0], [%1], 16;" :: "r"(s), "l"(gsrc));
}

// fp16 inputs, fp32 accumulate
#define MMAF(D, A, B) \
    asm volatile("mma.sync.aligned.m16n8k16.row.col.f32.f16.f16.f32 " \
                 "{%0,%1,%2,%3}, {%4,%5,%6,%7}, {%8,%9}, {%0,%1,%2,%3};" \
                 : "+f"((D)[0]), "+f"((D)[1]), "+f"((D)[2]), "+f"((D)[3]) \
                 : "r"((A)[0]), "r"((A)[1]), "r"((A)[2]), "r"((A)[3]), \
                   "r"((B)[0]), "r"((B)[1]))

// ---------------------------------------------------------------- prep
// t[p,r] = sum_s core2[r,h,s] * core3[s,w,0]
__global__ void k_t(const float* __restrict__ core2, const float* __restrict__ core3) {
    int idx = blockIdx.x * blockDim.x + threadIdx.x;
    if (idx >= HW_ * RS_) return;
    int r = idx & 31;
    int p = idx >> 5;
    int h = p / 48, w = p % 48;
    const float* c2 = core2 + (r * 48 + h) * 32;
    float s = 0.f;
#pragma unroll
    for (int si = 0; si < 32; si++) s += c2[si] * core3[si * 48 + w];
    g_T[p * 32 + r] = s;
}

// Ttrh[r][j] = fp16( core1[d,r] * t[p,r] ),  j = d*HW + p
__global__ void k_ttr(const float* __restrict__ core1) {
    int j = blockIdx.x * 256 + threadIdx.x;
    int r = blockIdx.y;
    int d = j / HW_;
    int p = j - d * HW_;
    g_Ttrh[(size_t)r * JJ_ + j] = __float2half_rn(core1[d * 32 + r] * g_T[p * 32 + r]);
}

// ---------------------------------------------------------------- gram (mma.sync)
// V[k,r] = fp16(x[k]) * fp16(Tt[k,r]) (HMUL2); G = V^T V.
// 6 upper m16n8 tiles, fp32 accumulate; lower triangle mirrored at writeout.
// 128-k tiles, 3-stage cp.async ring, prefetch distance 2, ONE barrier/tile.
__global__ void __launch_bounds__(256, 4) k_gram(const float* __restrict__ x) {
    __shared__ __half sTt[3][32][136];  // stride 136 halves (272B): conflict-free LDS.32
    __shared__ float  sX [3][8][128];

    int tid = threadIdx.x;
    int w   = tid >> 5;
    int l   = tid & 31;
    int n0  = blockIdx.x * 8;
    int ks  = blockIdx.y;
    size_t j0 = (size_t)ks * KPC_;

    int g   = l >> 2;          // row group 0..7
    int tg2 = (l & 3) * 2;     // col pair base

    float acc[6][4];
#pragma unroll
    for (int i = 0; i < 6; i++)
#pragma unroll
        for (int j = 0; j < 4; j++) acc[i][j] = 0.f;

    auto issue = [&](int t, int b) {
        size_t jt = j0 + (size_t)t * KTL_;
        // sTt: 32 rows x 16 chunks of 16B (fp16 row = 256B) = 512 chunks
        {
            int row = tid >> 3, ch = tid & 7;
            cp16(&sTt[b][row][ch * 8], g_Ttrh + (size_t)row * JJ_ + jt + ch * 8);
            cp16(&sTt[b][row][(ch + 8) * 8], g_Ttrh + (size_t)row * JJ_ + jt + (ch + 8) * 8);
        }
        // sX: 8 rows x 32 chunks of 16B = 256 chunks
        {
            int row = tid >> 5, ch = tid & 31;
            cp16(&sX[b][row][ch * 4], x + (size_t)(n0 + row) * JJ_ + jt + ch * 4);
        }
        asm volatile("cp.async.commit_group;" ::: "memory");
    };

    issue(0, 0);
    issue(1, 1);

    for (int t = 0; t < TILES_; t++) {
        int b = t % 3;
        asm volatile("cp.async.wait_group 1;" ::: "memory");
        __syncthreads();
        if (t + 2 < TILES_) issue(t + 2, (t + 2) % 3);
        else asm volatile("cp.async.commit_group;" ::: "memory");  // uniform group count

#pragma unroll
        for (int kk = 0; kk < 8; kk++) {
            int kb = kk * 16;
            float2 xA = *(const float2*)&sX[b][w][kb + tg2];
            float2 xB = *(const float2*)&sX[b][w][kb + tg2 + 8];
            __half2 xhA = __floats2half2_rn(xA.x, xA.y);   // low = even k
            __half2 xhB = __floats2half2_rn(xB.x, xB.y);

            unsigned ah[2][4];
#pragma unroll
            for (int rr = 0; rr < 4; rr++) {       // rows g, g+8, g+16, g+24
                int row = g + 8 * rr;
                __half2 tA = *(const __half2*)&sTt[b][row][kb + tg2];
                __half2 tB = *(const __half2*)&sTt[b][row][kb + tg2 + 8];
                __half2 hA = __hmul2(xhA, tA);
                __half2 hB = __hmul2(xhB, tB);
                int mt = rr >> 1, rg = rr & 1;
                ah[mt][rg]     = *reinterpret_cast<unsigned*>(&hA);
                ah[mt][rg + 2] = *reinterpret_cast<unsigned*>(&hB);
            }
            // B fragments are register subsets of A fragments (Gram property)
            unsigned bh[4][2] = {{ah[0][0], ah[0][2]}, {ah[0][1], ah[0][3]},
                                 {ah[1][0], ah[1][2]}, {ah[1][1], ah[1][3]}};

            // upper tiles: (0,0)(0,1)(0,2)(0,3)(1,2)(1,3); (1,0)(1,1) mirror of (0,2)(0,3)
            MMAF(acc[0], ah[0], bh[0]);
            MMAF(acc[1], ah[0], bh[1]);
            MMAF(acc[2], ah[0], bh[2]);
            MMAF(acc[3], ah[0], bh[3]);
            MMAF(acc[4], ah[1], bh[2]);
            MMAF(acc[5], ah[1], bh[3]);
        }
    }

    // --- writeout partial Gram (mirror upper-right tiles to lower-left)
    float* P = g_Gp + ((size_t)ks * NB_ + n0 + w) * RSQ_;
    const int mt_of[6] = {0, 0, 0, 0, 1, 1};
    const int nt_of[6] = {0, 1, 2, 3, 2, 3};
#pragma unroll
    for (int ti = 0; ti < 6; ti++) {
        int r0 = mt_of[ti] * 16 + g;
        int r1 = r0 + 8;
        int q  = nt_of[ti] * 8 + tg2;
        P[r0 * 32 + q]     = acc[ti][0];
        P[r0 * 32 + q + 1] = acc[ti][1];
        P[r1 * 32 + q]     = acc[ti][2];
        P[r1 * 32 + q + 1] = acc[ti][3];
        if (ti == 2 || ti == 3) {
            P[q * 32 + r0]       = acc[ti][0];
            P[(q + 1) * 32 + r0] = acc[ti][1];
            P[q * 32 + r1]       = acc[ti][2];
            P[(q + 1) * 32 + r1] = acc[ti][3];
        }
    }
}

// sum K-split partials (float2 per thread -> 1024 blocks for occupancy/BW)
__global__ void k_gsum() {
    int i2 = blockIdx.x * 256 + threadIdx.x;   // over 512*1024/2 float2s
    float2 s = {0.f, 0.f};
#pragma unroll
    for (int p = 0; p < KS_; p++) {
        float2 v = *((const float2*)(g_Gp + (size_t)p * NB_ * RSQ_) + i2);
        s.x += v.x; s.y += v.y;
    }
    *((float2*)g_G + i2) = s;
}

// ---------------------------------------------------------------- projection
// grid (16 ot, 256 kc) = 4096 blocks; 32-k steps, register-prefetch LDG pipeline
// + 3-buffer smem ring -> ONE barrier per step (buffer written at t was last
// read at t-3, ordered by intervening syncs).
__global__ void __launch_bounds__(256) k_proj(const float* __restrict__ projw) {
    __shared__ float sw[3][64][33];
    __shared__ float sf[3][16][33];
    int ot  = blockIdx.x;
    int kc  = blockIdx.y;
    int tid = threadIdx.x;
    int o0  = ot * 64;
    int b   = tid >> 4;
    int oo  = tid & 15;

    int orow = tid >> 2;
    int part = tid & 3;
    int frow = tid >> 4;
    int fcol = (tid & 15) * 2;

    float acc[4] = {0.f, 0.f, 0.f, 0.f};

    float4 w0, w1;
    float2 gv;
    auto ldg = [&](int kbase) {
        const float4* src = (const float4*)(projw + (size_t)(o0 + orow) * KK_ + kbase + part * 8);
        w0 = src[0];
        w1 = src[1];
        gv = *(const float2*)(g_G + (size_t)frow * KK_ + kbase + fcol);
    };

    ldg(kc * KCLP_);

    int nsteps = KCLP_ / 32;   // 4
#pragma unroll
    for (int st = 0; st < 4; st++) {
        int buf = st % 3;
        // store prefetched regs into smem ring
        {
            float* drow = &sw[buf][orow][part * 8];
            drow[0] = w0.x; drow[1] = w0.y; drow[2] = w0.z; drow[3] = w0.w;
            drow[4] = w1.x; drow[5] = w1.y; drow[6] = w1.z; drow[7] = w1.w;
            sf[buf][frow][fcol]     = gv.x;
            sf[buf][frow][fcol + 1] = gv.y;
        }
        __syncthreads();
        if (st + 1 < nsteps) ldg(kc * KCLP_ + (st + 1) * 32);  // lands under compute
#pragma unroll
        for (int k = 0; k < 32; k++) {
            float fv = sf[buf][b][k];
            acc[0] += fv * sw[buf][oo * 4 + 0][k];
            acc[1] += fv * sw[buf][oo * 4 + 1][k];
            acc[2] += fv * sw[buf][oo * 4 + 2][k];
            acc[3] += fv * sw[buf][oo * 4 + 3][k];
        }
    }
#pragma unroll
    for (int j = 0; j < 4; j++)
        g_part[(size_t)kc * (BB_ * OUT_) + b * OUT_ + o0 + oo * 4 + j] = acc[j];
}

__global__ void k_final(const float* __restrict__ projb, float* __restrict__ out) {
    int idx = blockIdx.x * blockDim.x + threadIdx.x;
    if (idx >= BB_ * OUT_) return;
    float s = projb[idx & (OUT_ - 1)];
#pragma unroll
    for (int kc = 0; kc < KCP_; kc++) s += g_part[kc * (BB_ * OUT_) + idx];
    out[idx] = s;
}

// ---------------------------------------------------------------- launch
extern "C" void kernel_launch(void* const* d_in, const int* in_sizes, int n_in,
                              void* d_out, int out_size) {
    const float* x     = (const float*)d_in[0];
    const float* core1 = (const float*)d_in[1];
    const float* core2 = (const float*)d_in[2];
    const float* core3 = (const float*)d_in[3];
    const float* projw = (const float*)d_in[4];
    const float* projb = (const float*)d_in[5];
    float* out = (float*)d_out;

    k_t<<<(HW_ * RS_ + 255) / 256, 256>>>(core2, core3);
    dim3 tg(JJ_ / 256, RS_);
    k_ttr<<<tg, 256>>>(core1);
    dim3 gg(NB_ / 8, KS_);
    k_gram<<<gg, 256>>>(x);
    k_gsum<<<(NB_ * RSQ_) / 512, 256>>>();
    dim3 pg(16, KCP_);
    k_proj<<<pg, 256>>>(projw);
    k_final<<<(BB_ * OUT_ + 255) / 256, 256>>>(projb, out);
}